// round 12
// baseline (speedup 1.0000x reference)
#include <cuda_runtime.h>
#include <cuda_fp16.h>
#include <cstdint>

#define NN 131072
#define DD 128
#define LL 16
#define PP 8192
#define KK 8
#define PKE (PP*KK)
#define LEVE (LL-1)
#define CH 64            // CTAs per chain
#define FWD_Q 9          // NT 64-row tiles per fwd warp-group
#define REV_Q 7          // NT tiles per rev warp-group (128*9 + 128*7 = 2048)

// ---------------- scratch ----------------
__device__ float  g_h[(size_t)NN*DD];
__device__ __half g_Mf[2*PP*DD];
__device__ __half g_Mb[2*PP*DD];
__device__ int    g_cnt[LEVE*PP];
__device__ int    g_rp[LEVE*(PP+1)];
__device__ int    g_fill[LEVE*PP];
__device__ int    g_col[LEVE*PKE];
__device__ unsigned g_bars[64];   // 0: fwd, 32: rev, 16: joint NT barrier

// fp16 fragment layouts (round-10 derivation)
#define A_FRAG_SZ (32*132)            // 4224 words
#define W_FRAG_SZ (128*66)            // 8448 words
__device__ unsigned g_wf[6*W_FRAG_SZ];   // 0 f_pre, 1 f_upd, 2 b_pre, 3 b_upd, 4 nt_w1, 5 nt_w2

// ---------------- helpers ----------------
__device__ __forceinline__ unsigned h2u(float a, float b) {
    const __half2 h = __floats2half2_rn(a, b);
    return *(const unsigned*)&h;
}
__device__ __forceinline__ void mma16(float* d, const unsigned* a, const unsigned* b) {
    asm("mma.sync.aligned.m16n8k16.row.col.f32.f16.f16.f32 "
        "{%0,%1,%2,%3},{%4,%5,%6,%7},{%8,%9},{%0,%1,%2,%3};"
        : "+f"(d[0]), "+f"(d[1]), "+f"(d[2]), "+f"(d[3])
        : "r"(a[0]), "r"(a[1]), "r"(a[2]), "r"(a[3]), "r"(b[0]), "r"(b[1]));
}
__device__ __forceinline__ void frag_storeA8(unsigned* sA, int r, int c8, const float* f) {
    unsigned* p = sA + (((r>>4)*8 + (c8>>1))*132) + ((r&7)*16) + 2*(c8&1) + ((r>>3)&1);
    p[0] = h2u(f[0],f[1]); p[4] = h2u(f[2],f[3]);
    p[8] = h2u(f[4],f[5]); p[12] = h2u(f[6],f[7]);
}
__device__ __forceinline__ void frag_storeA_h2(unsigned* sA, int r, int c, unsigned h2) {
    const int kl = c & 15;
    sA[(((r>>4)*8 + (c>>4))*132) + ((r&7)*16) + ((kl>>1)&3)*4 + 2*(kl>>3) + ((r>>3)&1)] = h2;
}
__device__ __forceinline__ void acc8(float* f, uint4 u) {
    const float2 a = __half22float2(*(const __half2*)&u.x);
    const float2 b = __half22float2(*(const __half2*)&u.y);
    const float2 c = __half22float2(*(const __half2*)&u.z);
    const float2 d = __half22float2(*(const __half2*)&u.w);
    f[0]+=a.x; f[1]+=a.y; f[2]+=b.x; f[3]+=b.y;
    f[4]+=c.x; f[5]+=c.y; f[6]+=d.x; f[7]+=d.y;
}

// ---------------- prep: fp16 W fragments + CSR count + barrier zero ----------------
#define CNTB 290
__global__ void prep_kernel(const float* w0, const float* w1, const float* w2,
                            const float* w3, const float* w4, const float* w5,
                            const int* __restrict__ src) {
    const int tid = threadIdx.x;
    if (blockIdx.x < 6) {
        const float* W;
        switch (blockIdx.x) {
            case 0: W = w0; break; case 1: W = w1; break; case 2: W = w2; break;
            case 3: W = w3; break; case 4: W = w4; break; default: W = w5; break;
        }
        __half* dh = (__half*)(g_wf + (size_t)blockIdx.x * W_FRAG_SZ);
        #pragma unroll
        for (int it = 0; it < 16; ++it) {
            const int idx = tid + 256*it;
            const int k = idx >> 5, c4 = idx & 31;
            const float4 v = ((const float4*)W)[idx];
            const float vv[4] = {v.x, v.y, v.z, v.w};
            const int kb = k >> 4, kl = k & 15;
            const int t = (kl >> 1) & 3, sel = kl >> 3;
            #pragma unroll
            for (int q = 0; q < 4; ++q) {
                const int c = c4*4 + q;
                const int word = ((c>>3)*8 + kb)*66 + ((c&7)*4 + t)*2 + sel;
                dh[word*2 + (k&1)] = __float2half(vv[q]);
            }
        }
        if (blockIdx.x == 0 && tid < 64) g_bars[tid] = 0;
    } else {
        const int b = blockIdx.x - 6;
        const int tot = LEVE*PKE;
        for (int e = b*256 + tid; e < tot; e += CNTB*256)
            atomicAdd(&g_cnt[(e >> 16)*PP + src[e]], 1);
    }
}

// ---------------- fp16 GEMM core: 64x128 tile, 8 warps ----------------
__device__ __forceinline__ void gemm16(const unsigned* __restrict__ sA,
                                       const unsigned* __restrict__ sW,
                                       int wm, int wn, int lane,
                                       float acc[2][4][4]) {
    #pragma unroll
    for (int i = 0; i < 2; ++i)
        #pragma unroll
        for (int j = 0; j < 4; ++j)
            #pragma unroll
            for (int q = 0; q < 4; ++q) acc[i][j][q] = 0.f;
    #pragma unroll
    for (int kb = 0; kb < 8; ++kb) {
        unsigned a[2][4];
        #pragma unroll
        for (int i = 0; i < 2; ++i) {
            const uint4 v = *(const uint4*)(sA + (((wm*2+i)*8 + kb)*132) + lane*4);
            a[i][0] = v.x; a[i][1] = v.y; a[i][2] = v.z; a[i][3] = v.w;
        }
        unsigned b[4][2];
        #pragma unroll
        for (int j = 0; j < 4; ++j) {
            const uint2 v = *(const uint2*)(sW + (((wn*4+j)*8 + kb)*66) + lane*2);
            b[j][0] = v.x; b[j][1] = v.y;
        }
        #pragma unroll
        for (int i = 0; i < 2; ++i)
            #pragma unroll
            for (int j = 0; j < 4; ++j)
                mma16(acc[i][j], a[i], b[j]);
    }
}

#define WG_BAR() asm volatile("bar.sync %0, 256;" :: "r"(1+wg) : "memory")

// ---------------- CG-style split grid sync (fence by CTA master only) ----------------
__device__ __forceinline__ void g_arrive(unsigned* ctr) {
    __syncthreads();
    if (threadIdx.x == 0) {
        __threadfence();                 // master-only release (CG sync_grids pattern)
        atomicAdd(ctr, 1u);
    }
}
__device__ __forceinline__ void g_wait(unsigned* ctr, unsigned tgt) {
    if (threadIdx.x == 0) {
        unsigned v;
        do {
            asm volatile("ld.acquire.gpu.global.u32 %0, [%1];" : "=r"(v) : "l"(ctr) : "memory");
        } while (v < tgt);
        __threadfence();                 // master-only acquire-side fence
    }
    __syncthreads();
}

// ---------------- mega persistent kernel: CSR scan/fill + NT + both MP chains ----------------
#define CH_SMEM ((2*W_FRAG_SZ + 2*A_FRAG_SZ + 256) * 4)

__global__ __launch_bounds__(512, 1) void mega_kernel(
    float* __restrict__ out,
    const float* __restrict__ x,
    const int* __restrict__ src,
    const float* __restrict__ nt_b1, const float* __restrict__ nt_b2,
    const float* __restrict__ f_pre_b, const float* __restrict__ f_upd_b,
    const float* __restrict__ b_pre_b, const float* __restrict__ b_upd_b)
{
    extern __shared__ unsigned sm[];
    unsigned* sWpre = sm;
    unsigned* sWupd = sm + W_FRAG_SZ;
    unsigned* sA0   = sm + 2*W_FRAG_SZ;
    unsigned* sA1   = sA0 + A_FRAG_SZ;
    float*    sB    = (float*)(sA1 + A_FRAG_SZ);

    const int tid = threadIdx.x, lane = tid & 31, w = tid >> 5;
    const int wg = w >> 3, lt = tid & 255;
    const int wm = (w >> 2) & 1, wn = w & 3;
    const int g = lane >> 2, t = lane & 3;
    const bool fwd = blockIdx.x < CH;
    const int cc = fwd ? blockIdx.x : blockIdx.x - CH;
    const int r0 = cc * 128;
    const int cofs = fwd ? 0 : 128;
    unsigned* ctr = &g_bars[fwd ? 0 : 32];
    __half* Mbase = fwd ? g_Mf : g_Mb;
    const unsigned* wfpre = g_wf + (size_t)(fwd ? 0 : 2) * W_FRAG_SZ;
    const unsigned* wfupd = g_wf + (size_t)(fwd ? 1 : 3) * W_FRAG_SZ;
    const float* preB = fwd ? f_pre_b : b_pre_b;
    const float* updB = fwd ? f_upd_b : b_upd_b;
    unsigned* sAw = wg ? sA1 : sA0;

    unsigned tgt = 0;

    // ============ rev CTAs: CSR scan (CTAs 0..14) + rev-sync + fill ============
    if (!fwd) {
        if (cc < LEVE) {
            const int lvl = cc;
            const int base = lvl*PP;
            int c[16]; int sum = 0;
            #pragma unroll
            for (int j = 0; j < 16; ++j) { c[j] = g_cnt[base + tid*16 + j]; sum += c[j]; }
            int* sh = (int*)sA0;
            sh[tid] = sum; __syncthreads();
            for (int d = 1; d < 512; d <<= 1) {
                int v = (tid >= d) ? sh[tid-d] : 0;
                __syncthreads();
                sh[tid] += v;
                __syncthreads();
            }
            int off = sh[tid] - sum;
            int* rpl = g_rp + lvl*(PP+1);
            #pragma unroll
            for (int j = 0; j < 16; ++j) {
                const int idx = tid*16 + j;
                rpl[idx] = off; g_fill[base + idx] = off; off += c[j];
            }
            if (tid == 511) rpl[PP] = off;
        }
        tgt += CH;
        g_arrive(ctr);
        g_wait(ctr, tgt);
        // fill (published by joint NT barrier below)
        const int tot = LEVE*PKE;
        for (int e = cc*512 + tid; e < tot; e += CH*512) {
            const int lvl = e >> 16;
            const int le  = e & (PKE-1);
            const int pos = atomicAdd(&g_fill[lvl*PP + src[e]], 1);
            g_col[(size_t)lvl*PKE + pos] = le >> 3;
        }
    }

    // ============ node transform section ============
    for (int i = tid; i < W_FRAG_SZ/4; i += 512) {
        ((uint4*)sWpre)[i] = ((const uint4*)(g_wf + (size_t)4*W_FRAG_SZ))[i];
        ((uint4*)sWupd)[i] = ((const uint4*)(g_wf + (size_t)5*W_FRAG_SZ))[i];
    }
    if (tid < 32) {
        ((float4*)sB)[tid]       = ((const float4*)nt_b1)[tid];
        ((float4*)(sB+128))[tid] = ((const float4*)nt_b2)[tid];
    }
    __syncthreads();

    {
        const int gid = cc*2 + wg;
        const int tq = fwd ? FWD_Q : REV_Q;
        const int tb = fwd ? gid*FWD_Q : (128*FWD_Q + gid*REV_Q);
        for (int i = 0; i < tq; ++i) {
            const int rn = (tb + i) * 64;
            #pragma unroll
            for (int it = 0; it < 4; ++it) {
                const int idx = lt + 256*it;
                const int r = idx >> 4, c8 = idx & 15;
                const float4 va = *(const float4*)(x + (size_t)(rn + r)*128 + c8*8);
                const float4 vb = *(const float4*)(x + (size_t)(rn + r)*128 + c8*8 + 4);
                const float f[8] = {va.x,va.y,va.z,va.w, vb.x,vb.y,vb.z,vb.w};
                frag_storeA8(sAw, r, c8, f);
            }
            WG_BAR();
            float acc[2][4][4];
            gemm16(sAw, sWpre, wm, wn, lane, acc);
            WG_BAR();
            #pragma unroll
            for (int ii = 0; ii < 2; ++ii) {
                const int rloc = wm*32 + ii*16 + g;
                #pragma unroll
                for (int j = 0; j < 4; ++j) {
                    const int c = wn*32 + j*8 + t*2;
                    const float b0 = sB[c], b1 = sB[c+1];
                    frag_storeA_h2(sAw, rloc,   c, h2u(fmaxf(acc[ii][j][0]+b0,0.f), fmaxf(acc[ii][j][1]+b1,0.f)));
                    frag_storeA_h2(sAw, rloc+8, c, h2u(fmaxf(acc[ii][j][2]+b0,0.f), fmaxf(acc[ii][j][3]+b1,0.f)));
                }
            }
            WG_BAR();
            float acc2[2][4][4];
            gemm16(sAw, sWupd, wm, wn, lane, acc2);
            #pragma unroll
            for (int ii = 0; ii < 2; ++ii) {
                const int rl = rn + wm*32 + ii*16 + g;
                #pragma unroll
                for (int j = 0; j < 4; ++j) {
                    const int c = wn*32 + j*8 + t*2;
                    const float b0 = sB[128+c], b1 = sB[128+c+1];
                    *(float2*)(g_h + (size_t)rl*128 + c)
                        = make_float2(acc2[ii][j][0]+b0, acc2[ii][j][1]+b1);
                    *(float2*)(g_h + (size_t)(rl+8)*128 + c)
                        = make_float2(acc2[ii][j][2]+b0, acc2[ii][j][3]+b1);
                }
            }
            WG_BAR();
        }
    }

    // joint barrier across all 128 CTAs (publishes h + CSR fill);
    // chain weight copy overlaps the wait
    g_arrive(&g_bars[16]);
    for (int i = tid; i < W_FRAG_SZ/4; i += 512) {
        ((uint4*)sWpre)[i] = ((const uint4*)wfpre)[i];
        ((uint4*)sWupd)[i] = ((const uint4*)wfupd)[i];
    }
    if (tid < 32) {
        ((float4*)sB)[tid]       = ((const float4*)preB)[tid];
        ((float4*)(sB+128))[tid] = ((const float4*)updB)[tid];
    }
    g_wait(&g_bars[16], 2*CH);

    // ============ boundary level ============
    {
        const int lvl0 = fwd ? 0 : LEVE;
        float4 y0[8];
        #pragma unroll
        for (int it = 0; it < 4; ++it) {
            const int idx = lt + 256*it;
            const int r = idx >> 4, c8 = idx & 15;
            const size_t node = (size_t)lvl0*PP + r0 + wg*64 + r;
            const float* hv = g_h + node*128 + c8*8;
            const float* ub = sB + 128 + c8*8;
            float f[8];
            #pragma unroll
            for (int q = 0; q < 8; ++q) f[q] = fmaxf(ub[q], 0.f) + hv[q];
            y0[2*it]   = make_float4(f[0],f[1],f[2],f[3]);
            y0[2*it+1] = make_float4(f[4],f[5],f[6],f[7]);
            frag_storeA8(sAw, r, c8, f);
        }
        WG_BAR();
        const int l1 = fwd ? 1 : (LEVE-1);
        __half* Mnext = Mbase + (size_t)(l1 & 1)*PP*DD;
        float acc[2][4][4];
        gemm16(sAw, sWpre, wm, wn, lane, acc);
        #pragma unroll
        for (int i = 0; i < 2; ++i) {
            const int rl = r0 + wg*64 + wm*32 + i*16 + g;
            #pragma unroll
            for (int j = 0; j < 4; ++j) {
                const int c = wn*32 + j*8 + t*2;
                const float b0 = sB[c], b1 = sB[c+1];
                *(__half2*)(Mnext + (size_t)rl*128 + c) =
                    __floats2half2_rn(fmaxf(acc[i][j][0]+b0,0.f), fmaxf(acc[i][j][1]+b1,0.f));
                *(__half2*)(Mnext + (size_t)(rl+8)*128 + c) =
                    __floats2half2_rn(fmaxf(acc[i][j][2]+b0,0.f), fmaxf(acc[i][j][3]+b1,0.f));
            }
        }
        tgt += CH;
        g_arrive(ctr);
        #pragma unroll
        for (int it = 0; it < 4; ++it) {
            const int idx = lt + 256*it;
            const int r = idx >> 4, c8 = idx & 15;
            const size_t node = (size_t)lvl0*PP + r0 + wg*64 + r;
            *(float4*)(out + node*256 + cofs + c8*8)     = y0[2*it];
            *(float4*)(out + node*256 + cofs + c8*8 + 4) = y0[2*it+1];
        }
        g_wait(ctr, tgt);
    }

    // ============ 15 levels ============
    for (int s = 0; s < LEVE; ++s) {
        const int l = fwd ? (1+s) : (LEVE-1-s);
        const bool last = (s == LEVE-1);
        __half* Mbuf = Mbase + (size_t)(l & 1)*PP*DD;

        // ---- gather-mean of M into sAw ----
        #pragma unroll
        for (int it = 0; it < 4; ++it) {
            const int idx = lt + 256*it;
            const int r = idx >> 4, c8 = idx & 15;
            const int pl = r0 + wg*64 + r;
            float f[8];
            #pragma unroll
            for (int q = 0; q < 8; ++q) f[q] = 0.f;
            float inv = 0.125f;
            if (fwd) {
                const int4* sp = (const int4*)(src + (size_t)(l-1)*PKE + pl*KK);
                const int4 ia = sp[0], ib = sp[1];
                acc8(f, *(const uint4*)(Mbuf + (size_t)ia.x*128 + c8*8));
                acc8(f, *(const uint4*)(Mbuf + (size_t)ia.y*128 + c8*8));
                acc8(f, *(const uint4*)(Mbuf + (size_t)ia.z*128 + c8*8));
                acc8(f, *(const uint4*)(Mbuf + (size_t)ia.w*128 + c8*8));
                acc8(f, *(const uint4*)(Mbuf + (size_t)ib.x*128 + c8*8));
                acc8(f, *(const uint4*)(Mbuf + (size_t)ib.y*128 + c8*8));
                acc8(f, *(const uint4*)(Mbuf + (size_t)ib.z*128 + c8*8));
                acc8(f, *(const uint4*)(Mbuf + (size_t)ib.w*128 + c8*8));
            } else {
                const int* rpl = g_rp + l*(PP+1);
                const int b0 = rpl[pl], e0 = rpl[pl+1];
                const int* colsl = g_col + (size_t)l*PKE;
                int jj = b0;
                for (; jj + 4 <= e0; jj += 4) {
                    const int d0 = colsl[jj], d1 = colsl[jj+1];
                    const int d2 = colsl[jj+2], d3 = colsl[jj+3];
                    const uint4 u0 = *(const uint4*)(Mbuf + (size_t)d0*128 + c8*8);
                    const uint4 u1 = *(const uint4*)(Mbuf + (size_t)d1*128 + c8*8);
                    const uint4 u2 = *(const uint4*)(Mbuf + (size_t)d2*128 + c8*8);
                    const uint4 u3 = *(const uint4*)(Mbuf + (size_t)d3*128 + c8*8);
                    acc8(f, u0); acc8(f, u1); acc8(f, u2); acc8(f, u3);
                }
                for (; jj < e0; ++jj)
                    acc8(f, *(const uint4*)(Mbuf + (size_t)colsl[jj]*128 + c8*8));
                inv = (e0 > b0) ? 1.0f/(float)(e0-b0) : 0.f;
            }
            #pragma unroll
            for (int q = 0; q < 8; ++q) f[q] *= inv;
            frag_storeA8(sAw, r, c8, f);
        }
        WG_BAR();

        // ---- update GEMM ----
        float acc[2][4][4];
        gemm16(sAw, sWupd, wm, wn, lane, acc);
        WG_BAR();

        // ---- epilogue: Y = relu(acc+updB)+h; keep Y in acc; frags for preGEMM ----
        #pragma unroll
        for (int i = 0; i < 2; ++i) {
            const int rloc = wm*32 + i*16 + g;
            const int rl = r0 + wg*64 + rloc;
            #pragma unroll
            for (int j = 0; j < 4; ++j) {
                const int c = wn*32 + j*8 + t*2;
                const float b0 = sB[128+c], b1 = sB[128+c+1];
                float v0 = fmaxf(acc[i][j][0]+b0, 0.f);
                float v1 = fmaxf(acc[i][j][1]+b1, 0.f);
                float v2 = fmaxf(acc[i][j][2]+b0, 0.f);
                float v3 = fmaxf(acc[i][j][3]+b1, 0.f);
                const size_t nlo = (size_t)l*PP + rl, nhi = nlo + 8;
                const float2 hlo = *(const float2*)(g_h + nlo*128 + c);
                const float2 hhi = *(const float2*)(g_h + nhi*128 + c);
                v0 += hlo.x; v1 += hlo.y; v2 += hhi.x; v3 += hhi.y;
                if (!last) {
                    frag_storeA_h2(sAw, rloc,   c, h2u(v0, v1));
                    frag_storeA_h2(sAw, rloc+8, c, h2u(v2, v3));
                }
                acc[i][j][0] = v0; acc[i][j][1] = v1;
                acc[i][j][2] = v2; acc[i][j][3] = v3;
            }
        }

        if (!last) {
            WG_BAR();
            const int lnext = fwd ? (l+1) : (l-1);
            __half* Mnext = Mbase + (size_t)(lnext & 1)*PP*DD;
            float acc2[2][4][4];
            gemm16(sAw, sWpre, wm, wn, lane, acc2);
            #pragma unroll
            for (int i = 0; i < 2; ++i) {
                const int rl = r0 + wg*64 + wm*32 + i*16 + g;
                #pragma unroll
                for (int j = 0; j < 4; ++j) {
                    const int c = wn*32 + j*8 + t*2;
                    const float b0 = sB[c], b1 = sB[c+1];
                    *(__half2*)(Mnext + (size_t)rl*128 + c) =
                        __floats2half2_rn(fmaxf(acc2[i][j][0]+b0,0.f), fmaxf(acc2[i][j][1]+b1,0.f));
                    *(__half2*)(Mnext + (size_t)(rl+8)*128 + c) =
                        __floats2half2_rn(fmaxf(acc2[i][j][2]+b0,0.f), fmaxf(acc2[i][j][3]+b1,0.f));
                }
            }
            tgt += CH;
            g_arrive(ctr);
        }

        // ---- out-write from Y held in acc (off the publish path) ----
        #pragma unroll
        for (int i = 0; i < 2; ++i) {
            const int rl = r0 + wg*64 + wm*32 + i*16 + g;
            #pragma unroll
            for (int j = 0; j < 4; ++j) {
                const int c = wn*32 + j*8 + t*2;
                const size_t nlo = (size_t)l*PP + rl, nhi = nlo + 8;
                *(float2*)(out + nlo*256 + cofs + c) = make_float2(acc[i][j][0], acc[i][j][1]);
                *(float2*)(out + nhi*256 + cofs + c) = make_float2(acc[i][j][2], acc[i][j][3]);
            }
        }

        if (!last) g_wait(ctr, tgt);
    }
}

// ---------------- launch ----------------
extern "C" void kernel_launch(void* const* d_in, const int* in_sizes, int n_in,
                              void* d_out, int out_size) {
    const float* x       = (const float*)d_in[0];
    const int*   src     = (const int*)  d_in[1];
    const float* nt_w1   = (const float*)d_in[2];
    const float* nt_b1   = (const float*)d_in[3];
    const float* nt_w2   = (const float*)d_in[4];
    const float* nt_b2   = (const float*)d_in[5];
    const float* f_pre_w = (const float*)d_in[6];
    const float* f_pre_b = (const float*)d_in[7];
    const float* f_upd_w = (const float*)d_in[8];
    const float* f_upd_b = (const float*)d_in[9];
    const float* b_pre_w = (const float*)d_in[10];
    const float* b_pre_b = (const float*)d_in[11];
    const float* b_upd_w = (const float*)d_in[12];
    const float* b_upd_b = (const float*)d_in[13];
    float* out = (float*)d_out;

    void* p_cnt;
    cudaGetSymbolAddress(&p_cnt, g_cnt);

    cudaFuncSetAttribute(mega_kernel, cudaFuncAttributeMaxDynamicSharedMemorySize, CH_SMEM);

    cudaMemsetAsync(p_cnt, 0, (size_t)LEVE*PP*sizeof(int));
    prep_kernel<<<6 + CNTB, 256>>>(f_pre_w, f_upd_w, b_pre_w, b_upd_w, nt_w1, nt_w2, src);
    mega_kernel<<<2*CH, 512, CH_SMEM>>>(out, x, src,
        nt_b1, nt_b2, f_pre_b, f_upd_b, b_pre_b, b_upd_b);
}